// round 14
// baseline (speedup 1.0000x reference)
#include <cuda_runtime.h>
#include <cuda_bf16.h>
#include <cstdint>
#include <math.h>

#define B_ 4
#define L_ 1024
#define D_ 1024
#define H_ 16
#define HD_ 64
#define F_ 2816
#define A_ 64
#define P_ 30
#define LP_ 1054
#define LPP 1088
#define NT_ 17

// ---------------- scratch ----------------
__device__ float g_x1[B_*L_*D_];
__device__ float g_y [B_*L_*D_];

__device__ __nv_bfloat16 g_xnh[B_*L_*D_], g_xnl[B_*L_*D_];
__device__ __nv_bfloat16 g_ench[B_*L_*D_], g_encl[B_*L_*D_];
__device__ __nv_bfloat16 g_aoh[B_*L_*D_], g_aol[B_*L_*D_];
__device__ __nv_bfloat16 g_gh[B_*L_*F_], g_gl[B_*L_*F_];

__device__ __nv_bfloat16 g_qh[B_*H_*L_*HD_],  g_ql[B_*H_*L_*HD_];
__device__ __nv_bfloat16 g_kh[B_*H_*LPP*HD_], g_kl[B_*H_*LPP*HD_];
__device__ __nv_bfloat16 g_vh[B_*H_*LPP*HD_], g_vl[B_*H_*LPP*HD_];

// combined weights
__device__ __nv_bfloat16 g_wqkvh[D_*3072], g_wqkvl[D_*3072];   // self Q|K|V
__device__ __nv_bfloat16 g_ckvh[D_*2048],  g_ckvl[D_*2048];    // cross K|V
__device__ __nv_bfloat16 g_cqh[D_*D_],     g_cql[D_*D_];
__device__ __nv_bfloat16 g_woh[D_*D_],     g_wol[D_*D_];
__device__ __nv_bfloat16 g_coh[D_*D_],     g_col[D_*D_];
__device__ __nv_bfloat16 g_w01h[D_*5632],  g_w01l[D_*5632];    // wi0/wi1 interleaved
__device__ __nv_bfloat16 g_wmh[F_*D_],     g_wml[F_*D_];

// adapter
__device__ __nv_bfloat16 g_adh[B_*D_*128], g_adl[B_*D_*128];
__device__ __nv_bfloat16 g_auh[B_*A_*D_], g_aul[B_*A_*D_];
__device__ __nv_bfloat16 g_azh[B_*L_*A_], g_azl[B_*L_*A_];

__device__ __forceinline__ float gelu_f(float x) {
    float x3 = x*x*x;
    return 0.5f*x*(1.0f + tanhf(0.7978845608028654f*(x + 0.044715f*x3)));
}
__device__ __forceinline__ uint32_t smem_u32(const void* p) {
    uint32_t a;
    asm("{ .reg .u64 t; cvta.to.shared.u64 t, %1; cvt.u32.u64 %0, t; }" : "=r"(a) : "l"(p));
    return a;
}
__device__ __forceinline__ void mma16816(float* d, const uint32_t* a, const uint32_t* b) {
    asm volatile("mma.sync.aligned.m16n8k16.row.col.f32.bf16.bf16.f32 "
        "{%0,%1,%2,%3}, {%4,%5,%6,%7}, {%8,%9}, {%0,%1,%2,%3};"
        : "+f"(d[0]), "+f"(d[1]), "+f"(d[2]), "+f"(d[3])
        : "r"(a[0]), "r"(a[1]), "r"(a[2]), "r"(a[3]), "r"(b[0]), "r"(b[1]));
}
__device__ __forceinline__ void ldsm4(uint32_t* r, uint32_t addr) {
    asm volatile("ldmatrix.sync.aligned.m8n8.x4.shared.b16 {%0,%1,%2,%3}, [%4];"
        : "=r"(r[0]), "=r"(r[1]), "=r"(r[2]), "=r"(r[3]) : "r"(addr));
}
__device__ __forceinline__ void ldsm4t(uint32_t* r, uint32_t addr) {
    asm volatile("ldmatrix.sync.aligned.m8n8.x4.trans.shared.b16 {%0,%1,%2,%3}, [%4];"
        : "=r"(r[0]), "=r"(r[1]), "=r"(r[2]), "=r"(r[3]) : "r"(addr));
}
__device__ __forceinline__ void cp16(uint32_t dst, const void* src) {
    asm volatile("cp.async.cg.shared.global [%0], [%1], 16;"
        :: "r"(dst), "l"(__cvta_generic_to_global(src)));
}
#define CP_COMMIT() asm volatile("cp.async.commit_group;" ::: "memory")
#define CP_WAIT0()  asm volatile("cp.async.wait_group 0;" ::: "memory")
#define CP_WAIT1()  asm volatile("cp.async.wait_group 1;" ::: "memory")

__device__ __forceinline__ void split_bf16(float x, __nv_bfloat16& h, __nv_bfloat16& l) {
    h = __float2bfloat16(x);
    l = __float2bfloat16(x - __bfloat162float(h));
}
__device__ __forceinline__ uint32_t packbf2(__nv_bfloat16 a, __nv_bfloat16 b) {
    __nv_bfloat162 t; t.x = a; t.y = b;
    return *(uint32_t*)&t;
}

// ---------------- rmsnorm -> bf16 planes ----------------
__global__ void __launch_bounds__(256) rmsnorm_k(const float* __restrict__ x,
                                                 const float* __restrict__ sc,
                                                 __nv_bfloat16* __restrict__ oh,
                                                 __nv_bfloat16* __restrict__ ol) {
    __shared__ float red[8];
    int row = blockIdx.x;
    const float* xr = x + (size_t)row * D_;
    float4 v = *(const float4*)(xr + threadIdx.x*4);
    float ss = v.x*v.x + v.y*v.y + v.z*v.z + v.w*v.w;
    #pragma unroll
    for (int off = 16; off; off >>= 1) ss += __shfl_xor_sync(0xffffffffu, ss, off);
    if ((threadIdx.x & 31) == 0) red[threadIdx.x >> 5] = ss;
    __syncthreads();
    if (threadIdx.x < 8) {
        float t = red[threadIdx.x];
        #pragma unroll
        for (int off = 4; off; off >>= 1) t += __shfl_xor_sync(0xffu, t, off);
        if (threadIdx.x == 0) red[0] = t;
    }
    __syncthreads();
    float rms = rsqrtf(red[0] * (1.0f / D_) + 1e-6f);
    float4 s4 = *(const float4*)(sc + threadIdx.x*4);
    float r0 = v.x*rms*s4.x, r1 = v.y*rms*s4.y, r2 = v.z*rms*s4.z, r3 = v.w*rms*s4.w;
    size_t base = (size_t)row * D_ + threadIdx.x*4;
    __nv_bfloat16 h0, l0, h1, l1, h2, l2, h3, l3;
    split_bf16(r0, h0, l0); split_bf16(r1, h1, l1);
    split_bf16(r2, h2, l2); split_bf16(r3, h3, l3);
    *(uint32_t*)(oh + base) = packbf2(h0, h1);
    *(uint32_t*)(oh + base + 2) = packbf2(h2, h3);
    *(uint32_t*)(ol + base) = packbf2(l0, l1);
    *(uint32_t*)(ol + base + 2) = packbf2(l2, l3);
}

// ---------------- fused multi-tensor split with layout transform ----------------
#define NSEG 12
struct SplitJobs {
    const float* src[NSEG];
    __nv_bfloat16* dh[NSEG];
    __nv_bfloat16* dl[NSEG];
    int blk_end[NSEG];
    int row_len[NSEG];
    int dst_stride[NSEG];
    int col_mul[NSEG];
    int col_off[NSEG];
};

__global__ void __launch_bounds__(256) wsplit_all(SplitJobs J) {
    int bid = blockIdx.x;
    int seg = 0;
    #pragma unroll
    for (int s = 0; s < NSEG; s++) { if (bid >= J.blk_end[s]) seg = s + 1; }
    int base = seg ? J.blk_end[seg-1] : 0;
    size_t i = (((size_t)(bid - base))*256 + threadIdx.x) * 4;
    int rl = J.row_len[seg];
    int k = (int)(i / rl);
    int col = (int)(i - (size_t)k*rl);
    size_t d = (size_t)k*J.dst_stride[seg] + (size_t)J.col_mul[seg]*col + J.col_off[seg];
    float4 v = *(const float4*)(J.src[seg] + i);
    __nv_bfloat16 h0, l0, h1, l1, h2, l2, h3, l3;
    split_bf16(v.x, h0, l0); split_bf16(v.y, h1, l1);
    split_bf16(v.z, h2, l2); split_bf16(v.w, h3, l3);
    __nv_bfloat16* dh = J.dh[seg];
    __nv_bfloat16* dl = J.dl[seg];
    if (J.col_mul[seg] == 1) {
        *(uint32_t*)(dh + d) = packbf2(h0, h1);
        *(uint32_t*)(dh + d + 2) = packbf2(h2, h3);
        *(uint32_t*)(dl + d) = packbf2(l0, l1);
        *(uint32_t*)(dl + d + 2) = packbf2(l2, l3);
    } else {
        dh[d] = h0; dh[d+2] = h1; dh[d+4] = h2; dh[d+6] = h3;
        dl[d] = l0; dl[d+2] = l1; dl[d+4] = l2; dl[d+6] = l3;
    }
}

// ---------------- adapter weight prep ----------------
__global__ void __launch_bounds__(256) adprep(const float* __restrict__ awd,
                                              const float* __restrict__ awu,
                                              __nv_bfloat16* __restrict__ adh,
                                              __nv_bfloat16* __restrict__ adl,
                                              __nv_bfloat16* __restrict__ auh,
                                              __nv_bfloat16* __restrict__ aul) {
    int idx = blockIdx.x*256 + threadIdx.x;
    const int NPAD = B_*D_*64;
    if (idx < NPAD) {
        int pa = idx & 63;
        int row = idx >> 6;
        uint32_t vh = 0, vl = 0;
        if (pa < 32) {
            float2 v = *(const float2*)(awd + (size_t)row*A_ + pa*2);
            __nv_bfloat16 h0, l0, h1, l1;
            split_bf16(v.x, h0, l0); split_bf16(v.y, h1, l1);
            vh = packbf2(h0, h1); vl = packbf2(l0, l1);
        }
        *(uint32_t*)(adh + (size_t)row*128 + pa*2) = vh;
        *(uint32_t*)(adl + (size_t)row*128 + pa*2) = vl;
    } else {
        int j = idx - NPAD;
        if (j < B_*A_*D_/2) {
            float2 v = *(const float2*)(awu + (size_t)j*2);
            __nv_bfloat16 h0, l0, h1, l1;
            split_bf16(v.x, h0, l0); split_bf16(v.y, h1, l1);
            *(uint32_t*)(auh + (size_t)j*2) = packbf2(h0, h1);
            *(uint32_t*)(aul + (size_t)j*2) = packbf2(l0, l1);
        }
    }
}

// ---------------- prefix KV copy ----------------
__global__ void __launch_bounds__(256) prefix_k(const float* __restrict__ pk,
                                                const float* __restrict__ pv,
                                                int sel,
                                                __nv_bfloat16* __restrict__ kh,
                                                __nv_bfloat16* __restrict__ kl,
                                                __nv_bfloat16* __restrict__ vh,
                                                __nv_bfloat16* __restrict__ vl) {
    int idx = blockIdx.x*256 + threadIdx.x;
    if (idx >= B_*P_*H_*HD_) return;
    int b = idx / (P_*H_*HD_);
    int rem = idx % (P_*H_*HD_);
    int p = rem >> 10;
    int h = (rem >> 6) & 15;
    int e = rem & 63;
    size_t src = (((size_t)(b*2 + sel)*P_ + p)*H_ + h)*HD_ + e;
    size_t dst = (((size_t)(b*H_ + h))*LPP + p)*HD_ + e;
    __nv_bfloat16 hh, ll;
    split_bf16(pk[src], hh, ll);
    kh[dst] = hh; kl[dst] = ll;
    split_bf16(pv[src], hh, ll);
    vh[dst] = hh; vl[dst] = ll;
}

// ============== mma.sync bf16-split GEMM ==============
// modes: 0 = fp32 C (+R)
//        2 = Q planes via Ch/Cl [b][h][l][e]
//        4 = adapter down (bias+gelu -> planes, cols<64)
//        5 = adapter up (C += v + bias)
//        6 = self QKV fused (N=3072): Q|K|V planes via globals
//        7 = cross KV fused (N=2048): K|V planes via globals
//        8 = gated MLP (N=5632 interleaved): gelu(even)*odd -> Ch/Cl at [rr][col/2]
#define GMMA_SMEM (2*65536)

__device__ __forceinline__ void g_load_stage(
    uint32_t base, int tid, int m0, int n0, int k0, int K, int N,
    const __nv_bfloat16* Ah, const __nv_bfloat16* Al,
    const __nv_bfloat16* Bh, const __nv_bfloat16* Bl)
{
    #pragma unroll
    for (int pl = 0; pl < 2; pl++) {
        const __nv_bfloat16* Ap = pl ? Al : Ah;
        uint32_t ab = base + pl*16384;
        #pragma unroll
        for (int i = 0; i < 4; i++) {
            int idx = tid + i*256;
            int row = idx >> 3, c = idx & 7;
            uint32_t dst = ab + row*128 + ((c ^ (row & 7)) << 4);
            cp16(dst, Ap + (size_t)(m0 + row)*K + k0 + c*8);
        }
        const __nv_bfloat16* Bp = pl ? Bl : Bh;
        uint32_t bb = base + 32768 + pl*16384;
        #pragma unroll
        for (int i = 0; i < 4; i++) {
            int idx = tid + i*256;
            int row = idx >> 4, c = idx & 15;
            uint32_t cc = (c & 8) | ((c & 7) ^ (row & 7));
            uint32_t dst = bb + row*256 + (cc << 4);
            cp16(dst, Bp + (size_t)(k0 + row)*N + n0 + c*8);
        }
    }
}

__global__ void __launch_bounds__(256) gemm_mma(
    const __nv_bfloat16* __restrict__ Ah, const __nv_bfloat16* __restrict__ Al,
    const __nv_bfloat16* __restrict__ Bh, const __nv_bfloat16* __restrict__ Bl,
    float* __restrict__ C, const float* __restrict__ R,
    __nv_bfloat16* __restrict__ Ch, __nv_bfloat16* __restrict__ Cl,
    int K, int N, int mode, float scale,
    size_t bsA, size_t bsB, size_t bsC, const float* __restrict__ bias)
{
    extern __shared__ __align__(1024) char smem[];
    uint32_t sb = smem_u32(smem);
    const int tid = threadIdx.x;
    const int wid = tid >> 5, lane = tid & 31;
    const int warp_m = wid & 3, warp_n = wid >> 2;
    const int m0 = blockIdx.y*128, n0 = blockIdx.x*128;
    const size_t z = blockIdx.z;
    Ah += z*bsA; Al += z*bsA;
    Bh += z*bsB; Bl += z*bsB;

    float acc[16][4] = {};

    const int S = K >> 6;
    g_load_stage(sb, tid, m0, n0, 0, K, N, Ah, Al, Bh, Bl);
    CP_COMMIT();

    for (int s = 0; s < S; s++) {
        if (s + 1 < S) {
            g_load_stage(sb + ((s+1)&1)*65536, tid, m0, n0, (s+1)*64, K, N, Ah, Al, Bh, Bl);
            CP_COMMIT();
            CP_WAIT1();
        } else {
            CP_WAIT0();
        }
        __syncthreads();
        uint32_t base = sb + (s&1)*65536;

        #pragma unroll
        for (int c16 = 0; c16 < 4; c16++) {
            uint32_t ah[2][4], al[2][4];
            #pragma unroll
            for (int mt = 0; mt < 2; mt++) {
                int r = warp_m*32 + mt*16 + (lane & 15);
                int colc = c16*2 + (lane >> 4);
                uint32_t a = base + r*128 + (((uint32_t)(colc ^ (r & 7))) << 4);
                ldsm4(ah[mt], a);
                ldsm4(al[mt], a + 16384);
            }
            uint32_t bh[8][2], bl[8][2];
            #pragma unroll
            for (int j = 0; j < 4; j++) {
                int kr = c16*16 + (lane & 15);
                int ncol = warp_n*8 + j*2 + (lane >> 4);
                uint32_t cc = (ncol & 8) | ((ncol & 7) ^ (kr & 7));
                uint32_t addr = base + 32768 + kr*256 + (cc << 4);
                uint32_t t[4];
                ldsm4t(t, addr);
                bh[2*j][0] = t[0]; bh[2*j][1] = t[1];
                bh[2*j+1][0] = t[2]; bh[2*j+1][1] = t[3];
                ldsm4t(t, addr + 16384);
                bl[2*j][0] = t[0]; bl[2*j][1] = t[1];
                bl[2*j+1][0] = t[2]; bl[2*j+1][1] = t[3];
            }
            #pragma unroll
            for (int mt = 0; mt < 2; mt++) {
                #pragma unroll
                for (int nt = 0; nt < 8; nt++) {
                    float* d = acc[mt*8 + nt];
                    mma16816(d, ah[mt], bh[nt]);
                    mma16816(d, al[mt], bh[nt]);
                    mma16816(d, ah[mt], bl[nt]);
                }
            }
        }
        __syncthreads();
    }

    // epilogue
    #pragma unroll
    for (int mt = 0; mt < 2; mt++) {
        #pragma unroll
        for (int nt = 0; nt < 8; nt++) {
            float* a4 = acc[mt*8 + nt];
            int r = m0 + warp_m*32 + mt*16 + (lane >> 2);
            int col = n0 + warp_n*64 + nt*8 + (lane & 3)*2;
            #pragma unroll
            for (int half = 0; half < 2; half++) {
                int rr = r + half*8;
                float2 v = make_float2(a4[half*2]*scale, a4[half*2 + 1]*scale);
                if (mode == 0) {
                    size_t off = (size_t)rr*N + col;
                    if (R) { v.x += R[off]; v.y += R[off + 1]; }
                    *(float2*)(C + off) = v;
                } else if (mode == 6) {
                    int b = rr >> 10, l = rr & 1023;
                    int e = col & 63;
                    __nv_bfloat16 h0, l0, h1, l1;
                    if (col < 1024) {
                        v.x *= 0.125f; v.y *= 0.125f;
                        split_bf16(v.x, h0, l0); split_bf16(v.y, h1, l1);
                        size_t bo = (((size_t)(b*H_ + (col >> 6)))*1024 + l)*64 + e;
                        *(uint32_t*)(g_qh + bo) = packbf2(h0, h1);
                        *(uint32_t*)(g_ql + bo) = packbf2(l0, l1);
                    } else if (col < 2048) {
                        split_bf16(v.x, h0, l0); split_bf16(v.y, h1, l1);
                        size_t bo = (((size_t)(b*H_ + ((col - 1024) >> 6)))*LPP + l + P_)*64 + e;
                        *(uint32_t*)(g_kh + bo) = packbf2(h0, h1);
                        *(uint32_t*)(g_kl + bo) = packbf2(l0, l1);
                    } else {
                        split_bf16(v.x, h0, l0); split_bf16(v.y, h1, l1);
                        size_t bo = (((size_t)(b*H_ + ((col - 2048) >> 6)))*LPP + l + P_)*64 + e;
                        *(uint32_t*)(g_vh + bo) = packbf2(h0, h1);
                        *(uint32_t*)(g_vl + bo) = packbf2(l0, l1);
                    }
                } else if (mode == 7) {
                    int b = rr >> 10, l = rr & 1023;
                    int e = col & 63;
                    __nv_bfloat16 h0, l0, h1, l1;
                    split_bf16(v.x, h0, l0); split_bf16(v.y, h1, l1);
                    if (col < 1024) {
                        size_t bo = (((size_t)(b*H_ + (col >> 6)))*LPP + l + P_)*64 + e;
                        *(uint32_t*)(g_kh + bo) = packbf2(h0, h1);
                        *(uint32_t*)(g_kl + bo) = packbf2(l0, l1);
                    } else {
                        size_t bo = (((size_t)(b*H_ + ((col - 1024) >> 6)))*LPP + l + P_)*64 + e;
                        *(uint32_t*)(g_vh + bo) = packbf2(h0, h1);
                        *(uint32_t*)(g_vl + bo) = packbf2(l0, l1);
                    }
                } else if (mode == 8) {
                    float g = gelu_f(v.x) * v.y;
                    __nv_bfloat16 h0, l0;
                    split_bf16(g, h0, l0);
                    size_t bo = (size_t)rr*F_ + (col >> 1);
                    Ch[bo] = h0; Cl[bo] = l0;
                } else if (mode == 2) {
                    int b = rr >> 10, l = rr & 1023;
                    int hh = col >> 6, e = col & 63;
                    size_t bo = (((size_t)(b*H_ + hh))*1024 + l)*64 + e;
                    __nv_bfloat16 h0, l0, h1, l1;
                    split_bf16(v.x, h0, l0); split_bf16(v.y, h1, l1);
                    *(uint32_t*)(Ch + bo) = packbf2(h0, h1);
                    *(uint32_t*)(Cl + bo) = packbf2(l0, l1);
                } else if (mode == 4) {
                    if (col < 64) {
                        const float* bd = bias + z*A_;
                        v.x = gelu_f(v.x + bd[col]);
                        v.y = gelu_f(v.y + bd[col + 1]);
                        __nv_bfloat16 h0, l0, h1, l1;
                        split_bf16(v.x, h0, l0); split_bf16(v.y, h1, l1);
                        size_t bo = z*bsC + (size_t)rr*64 + col;
                        *(uint32_t*)(Ch + bo) = packbf2(h0, h1);
                        *(uint32_t*)(Cl + bo) = packbf2(l0, l1);
                    }
                } else {  // mode 5
                    const float* bu = bias + z*D_;
                    size_t off = z*bsC + (size_t)rr*N + col;
                    float2 cc = *(float2*)(C + off);
                    cc.x += v.x + bu[col];
                    cc.y += v.y + bu[col + 1];
                    *(float2*)(C + off) = cc;
                }
            }
        }
    }
}

// ================= mma.sync flash attention =================
#define AT_SMEM 87296

__global__ void __launch_bounds__(256) attn_mma(
    const __nv_bfloat16* __restrict__ Qhp, const __nv_bfloat16* __restrict__ Qlp,
    const __nv_bfloat16* __restrict__ Khp, const __nv_bfloat16* __restrict__ Klp,
    const __nv_bfloat16* __restrict__ Vhp, const __nv_bfloat16* __restrict__ Vlp,
    const float* __restrict__ relpos,
    __nv_bfloat16* __restrict__ Oh, __nv_bfloat16* __restrict__ Ol,
    int causal, int use_bias)
{
    extern __shared__ __align__(1024) char sm[];
    uint32_t sb = smem_u32(sm);
    const uint32_t sQ = sb;
    const uint32_t sStage = sb + 16384;
    float* bv   = (float*)(sm + 81920);
    float* wmax = (float*)(sm + 86272);
    float* wsum = (float*)(sm + 86784);

    const int tid = threadIdx.x;
    const int lane = tid & 31, wid = tid >> 5;
    const int warp_m = wid & 3, warp_n = wid >> 2;
    const int q0 = blockIdx.x*64, h = blockIdx.y, b = blockIdx.z;
    const int bh = b*H_ + h;
    const int r0 = lane >> 2;

    {
        const __nv_bfloat16* qg  = Qhp + ((size_t)bh*L_ + q0)*64;
        const __nv_bfloat16* qg2 = Qlp + ((size_t)bh*L_ + q0)*64;
        #pragma unroll
        for (int i = 0; i < 2; i++) {
            int idx = tid + i*256;
            int row = idx >> 3, c = idx & 7;
            uint32_t sw = row*128 + ((c ^ (row & 7)) << 4);
            cp16(sQ + sw, qg + row*64 + c*8);
            cp16(sQ + 8192 + sw, qg2 + row*64 + c*8);
        }
    }
    if (use_bias) {
        for (int d = tid; d < LPP; d += 256) {
            int bb;
            if (d < 16) bb = d;
            else {
                float t = logf((float)d / 16.0f) / 2.0794415416798357f * 16.0f;
                bb = 16 + (int)t;
                if (bb > 31) bb = 31;
            }
            bv[d] = relpos[h*32 + bb];
        }
    }

    const size_t kvbase = (size_t)bh * LPP * 64;
    const __nv_bfloat16* Kh = Khp + kvbase;
    const __nv_bfloat16* Kl = Klp + kvbase;
    const __nv_bfloat16* Vh = Vhp + kvbase;
    const __nv_bfloat16* Vl = Vlp + kvbase;

    int nk = NT_;
    if (causal) { int t = (q0 + 63 + P_)/64 + 1; if (t < nk) nk = t; }

    {
        uint32_t base = sStage;
        const __nv_bfloat16* ptrs[4] = { Kh, Kl, Vh, Vl };
        #pragma unroll
        for (int pl = 0; pl < 4; pl++)
            #pragma unroll
            for (int i = 0; i < 2; i++) {
                int idx = tid + i*256;
                int row = idx >> 3, c = idx & 7;
                uint32_t sw = row*128 + ((c ^ (row & 7)) << 4);
                cp16(base + pl*8192 + sw, ptrs[pl] + (size_t)row*64 + c*8);
            }
    }
    CP_COMMIT();

    float m_run[2] = {-1e30f, -1e30f};
    float l_run[2] = {0.0f, 0.0f};
    float oacc[8][4] = {};

    for (int s = 0; s < nk; s++) {
        if (s + 1 < nk) {
            uint32_t base = sStage + ((s+1)&1)*32768;
            const __nv_bfloat16* ptrs[4] = { Kh, Kl, Vh, Vl };
            #pragma unroll
            for (int pl = 0; pl < 4; pl++)
                #pragma unroll
                for (int i = 0; i < 2; i++) {
                    int idx = tid + i*256;
                    int row = idx >> 3, c = idx & 7;
                    uint32_t sw = row*128 + ((c ^ (row & 7)) << 4);
                    cp16(base + pl*8192 + sw, ptrs[pl] + (size_t)((s+1)*64 + row)*64 + c*8);
                }
            CP_COMMIT();
            CP_WAIT1();
        } else {
            CP_WAIT0();
        }
        __syncthreads();
        uint32_t kbuf = sStage + (s&1)*32768;
        uint32_t vbuf = kbuf + 16384;

        float sacc[4][4] = {};
        #pragma unroll
        for (int kc = 0; kc < 4; kc++) {
            uint32_t qa[4], qla[4];
            {
                int row = warp_m*16 + (lane & 15);
                int chunk = 2*kc + (lane >> 4);
                uint32_t a = sQ + row*128 + (((uint32_t)(chunk ^ (row & 7))) << 4);
                ldsm4(qa, a);
                ldsm4(qla, a + 8192);
            }
            uint32_t kbh[4][2], kbl2[4][2];
            #pragma unroll
            for (int half = 0; half < 2; half++) {
                int g = lane >> 3, l8 = lane & 7;
                int nrow = warp_n*32 + half*16 + ((g & 2) ? 8 : 0) + l8;
                int chunk = 2*kc + (g & 1);
                uint32_t a = kbuf + nrow*128 + (((uint32_t)(chunk ^ (nrow & 7))) << 4);
                uint32_t t[4];
                ldsm4(t, a);
                kbh[half*2][0] = t[0]; kbh[half*2][1] = t[1];
                kbh[half*2+1][0] = t[2]; kbh[half*2+1][1] = t[3];
                ldsm4(t, a + 8192);
                kbl2[half*2][0] = t[0]; kbl2[half*2][1] = t[1];
                kbl2[half*2+1][0] = t[2]; kbl2[half*2+1][1] = t[3];
            }
            #pragma unroll
            for (int nt = 0; nt < 4; nt++) {
                mma16816(sacc[nt], qa, kbh[nt]);
                mma16816(sacc[nt], qla, kbh[nt]);
                mma16816(sacc[nt], qa, kbl2[nt]);
            }
        }

        const int kt64 = s*64;
        const int rbase = q0 + warp_m*16 + r0;
        #pragma unroll
        for (int nt = 0; nt < 4; nt++) {
            #pragma unroll
            for (int half = 0; half < 2; half++) {
                #pragma unroll
                for (int j = 0; j < 2; j++) {
                    int key = kt64 + warp_n*32 + nt*8 + (lane & 3)*2 + j;
                    float v = sacc[nt][half*2 + j];
                    if (key >= LP_) v = -1e10f;
                    else if (causal && key >= P_) {
                        int d = (rbase + half*8) - (key - P_);
                        if (d < 0) v = -1e10f;
                        else if (use_bias) v += bv[d];
                    }
                    sacc[nt][half*2 + j] = v;
                }
            }
        }

        float mx[2] = {-1e30f, -1e30f};
        #pragma unroll
        for (int nt = 0; nt < 4; nt++) {
            mx[0] = fmaxf(mx[0], fmaxf(sacc[nt][0], sacc[nt][1]));
            mx[1] = fmaxf(mx[1], fmaxf(sacc[nt][2], sacc[nt][3]));
        }
        mx[0] = fmaxf(mx[0], __shfl_xor_sync(0xffffffffu, mx[0], 1));
        mx[0] = fmaxf(mx[0], __shfl_xor_sync(0xffffffffu, mx[0], 2));
        mx[1] = fmaxf(mx[1], __shfl_xor_sync(0xffffffffu, mx[1], 1));
        mx[1] = fmaxf(mx[1], __shfl_xor_sync(0xffffffffu, mx[1], 2));
        if ((lane & 3) == 0) {
            wmax[warp_n*64 + warp_m*16 + r0] = mx[0];
            wmax[warp_n*64 + warp_m*16 + r0 + 8] = mx[1];
        }
        __syncthreads();
        float mn[2], corr[2];
        #pragma unroll
        for (int half = 0; half < 2; half++) {
            int rr = warp_m*16 + r0 + half*8;
            float mt = fmaxf(wmax[rr], wmax[64 + rr]);
            mn[half] = fmaxf(m_run[half], mt);
            corr[half] = __expf(m_run[half] - mn[half]);
        }
        float rs[2] = {0.0f, 0.0f};
        #pragma unroll
        for (int nt = 0; nt < 4; nt++) {
            #pragma unroll
            for (int half = 0; half < 2; half++) {
                #pragma unroll
                for (int j = 0; j < 2; j++) {
                    float p = __expf(sacc[nt][half*2 + j] - mn[half]);
                    sacc[nt][half*2 + j] = p;
                    rs[half] += p;
                }
            }
        }
        rs[0] += __shfl_xor_sync(0xffffffffu, rs[0], 1);
        rs[0] += __shfl_xor_sync(0xffffffffu, rs[0], 2);
        rs[1] += __shfl_xor_sync(0xffffffffu, rs[1], 1);
        rs[1] += __shfl_xor_sync(0xffffffffu, rs[1], 2);
        if ((lane & 3) == 0) {
            wsum[warp_n*64 + warp_m*16 + r0] = rs[0];
            wsum[warp_n*64 + warp_m*16 + r0 + 8] = rs[1];
        }
        __syncthreads();
        #pragma unroll
        for (int half = 0; half < 2; half++) {
            int rr = warp_m*16 + r0 + half*8;
            l_run[half] = l_run[half]*corr[half] + wsum[rr] + wsum[64 + rr];
            m_run[half] = mn[half];
        }

        #pragma unroll
        for (int nt = 0; nt < 8; nt++) {
            oacc[nt][0] *= corr[0]; oacc[nt][1] *= corr[0];
            oacc[nt][2] *= corr[1]; oacc[nt][3] *= corr[1];
        }

        #pragma unroll
        for (int kc2 = 0; kc2 < 2; kc2++) {
            uint32_t pah[4], pal[4];
            {
                __nv_bfloat16 h0, l0, h1, l1;
                split_bf16(sacc[2*kc2][0], h0, l0); split_bf16(sacc[2*kc2][1], h1, l1);
                pah[0] = packbf2(h0, h1); pal[0] = packbf2(l0, l1);
                split_bf16(sacc[2*kc2][2], h0, l0); split_bf16(sacc[2*kc2][3], h1, l1);
                pah[1] = packbf2(h0, h1); pal[1] = packbf2(l0, l1);
                split_bf16(sacc[2*kc2+1][0], h0, l0); split_bf16(sacc[2*kc2+1][1], h1, l1);
                pah[2] = packbf2(h0, h1); pal[2] = packbf2(l0, l1);
                split_bf16(sacc[2*kc2+1][2], h0, l0); split_bf16(sacc[2*kc2+1][3], h1, l1);
                pah[3] = packbf2(h0, h1); pal[3] = packbf2(l0, l1);
            }
            uint32_t vbh[8][2], vbl[8][2];
            #pragma unroll
            for (int eg = 0; eg < 4; eg++) {
                int kr = warp_n*32 + kc2*16 + (lane & 15);
                int chunk = 2*eg + (lane >> 4);
                uint32_t a = vbuf + kr*128 + (((uint32_t)(chunk ^ (kr & 7))) << 4);
                uint32_t t[4];
                ldsm4t(t, a);
                vbh[eg*2][0] = t[0]; vbh[eg*2][1] = t[1];
                vbh[eg*2+1][0] = t[2]; vbh[eg*2+1][1] = t[3];
                ldsm4t(t, a + 8192);
                vbl[eg*2][0] = t[0]; vbl[eg*2][1] = t[1];
                vbl[eg*2+1][0] = t[2]; vbl[eg*2+1][1] = t[3];
            }
            #pragma unroll
            for (int nt = 0; nt < 8; nt++) {
                mma16816(oacc[nt], pah, vbh[nt]);
                mma16816(oacc[nt], pal, vbh[nt]);
                mma16816(oacc[nt], pah, vbl[nt]);
            }
        }
        __syncthreads();
    }

    float inv[2] = {1.0f / l_run[0], 1.0f / l_run[1]};
    float* ocomb = (float*)(sm + 16384);
    if (warp_n == 1) {
        #pragma unroll
        for (int nt = 0; nt < 8; nt++) {
            #pragma unroll
            for (int half = 0; half < 2; half++) {
                int row = warp_m*16 + r0 + half*8;
                int col = nt*8 + (lane & 3)*2;
                *(float2*)(ocomb + row*64 + col) =
                    make_float2(oacc[nt][half*2], oacc[nt][half*2 + 1]);
            }
        }
    }
    __syncthreads();
    if (warp_n == 0) {
        #pragma unroll
        for (int nt = 0; nt < 8; nt++) {
            #pragma unroll
            for (int half = 0; half < 2; half++) {
                int row = warp_m*16 + r0 + half*8;
                int col = nt*8 + (lane & 3)*2;
                float2 o2 = *(float2*)(ocomb + row*64 + col);
                float v0 = (oacc[nt][half*2] + o2.x) * inv[half];
                float v1 = (oacc[nt][half*2 + 1] + o2.y) * inv[half];
                __nv_bfloat16 h0, l0, h1, l1;
                split_bf16(v0, h0, l0); split_bf16(v1, h1, l1);
                size_t base = (((size_t)(b*L_ + q0 + row))*H_ + h)*HD_ + col;
                *(uint32_t*)(Oh + base) = packbf2(h0, h1);
                *(uint32_t*)(Ol + base) = packbf2(l0, l1);
            }
        }
    }
}

// ---------------- host launcher ----------------
extern "C" void kernel_launch(void* const* d_in, const int* in_sizes, int n_in,
                              void* d_out, int out_size) {
    const float* inputs  = (const float*)d_in[0];
    const float* encoded = (const float*)d_in[1];
    const float* awd     = (const float*)d_in[2];
    const float* awu     = (const float*)d_in[3];
    const float* abd     = (const float*)d_in[4];
    const float* abu     = (const float*)d_in[5];
    const float* pk      = (const float*)d_in[6];
    const float* pv      = (const float*)d_in[7];
    const float* ln1     = (const float*)d_in[8];
    const float* ln2     = (const float*)d_in[9];
    const float* ln3     = (const float*)d_in[10];
    const float* sa_wq   = (const float*)d_in[11];
    const float* sa_wk   = (const float*)d_in[12];
    const float* sa_wv   = (const float*)d_in[13];
    const float* sa_wo   = (const float*)d_in[14];
    const float* ca_wq   = (const float*)d_in[15];
    const float* ca_wk   = (const float*)d_in[16];
    const float* ca_wv   = (const float*)d_in[17];
    const float* ca_wo   = (const float*)d_in[18];
    const float* relpos  = (const float*)d_in[19];
    const float* wi0     = (const float*)d_in[20];
    const float* wi1     = (const float*)d_in[21];
    const float* mwo     = (const float*)d_in[22];
    float* out = (float*)d_out;

    float *x1, *y;
    cudaGetSymbolAddress((void**)&x1, g_x1);
    cudaGetSymbolAddress((void**)&y,  g_y);

    __nv_bfloat16 *xnh, *xnl, *ench, *encl, *aoh, *aol, *gh, *gl;
    __nv_bfloat16 *qh, *ql, *kh, *kl, *vh, *vl;
    cudaGetSymbolAddress((void**)&xnh, g_xnh); cudaGetSymbolAddress((void**)&xnl, g_xnl);
    cudaGetSymbolAddress((void**)&ench, g_ench); cudaGetSymbolAddress((void**)&encl, g_encl);
    cudaGetSymbolAddress((void**)&aoh, g_aoh); cudaGetSymbolAddress((void**)&aol, g_aol);
    cudaGetSymbolAddress((void**)&gh, g_gh); cudaGetSymbolAddress((void**)&gl, g_gl);
    cudaGetSymbolAddress((void**)&qh, g_qh); cudaGetSymbolAddress((void**)&ql, g_ql);
    cudaGetSymbolAddress((void**)&kh, g_kh); cudaGetSymbolAddress((void**)&kl, g_kl);
    cudaGetSymbolAddress((void**)&vh, g_vh); cudaGetSymbolAddress((void**)&vl, g_vl);

    __nv_bfloat16 *wqkvh,*wqkvl,*ckvh,*ckvl,*cqh,*cql,*woh,*wol,*coh,*col_;
    __nv_bfloat16 *w01h,*w01l,*wmh,*wml;
    __nv_bfloat16 *adh,*adl,*auh,*aul,*azh,*azl;
    cudaGetSymbolAddress((void**)&wqkvh, g_wqkvh); cudaGetSymbolAddress((void**)&wqkvl, g_wqkvl);
    cudaGetSymbolAddress((void**)&ckvh, g_ckvh); cudaGetSymbolAddress((void**)&ckvl, g_ckvl);
    cudaGetSymbolAddress((void**)&cqh, g_cqh); cudaGetSymbolAddress((void**)&cql, g_cql);
    cudaGetSymbolAddress((void**)&woh, g_woh); cudaGetSymbolAddress((void**)&wol, g_wol);
    cudaGetSymbolAddress((void**)&coh, g_coh); cudaGetSymbolAddress((void**)&col_, g_col);
    cudaGetSymbolAddress((void**)&w01h, g_w01h); cudaGetSymbolAddress((void**)&w01l, g_w01l);
    cudaGetSymbolAddress((void**)&wmh, g_wmh); cudaGetSymbolAddress((void**)&wml, g_wml);
    cudaGetSymbolAddress((void**)&adh, g_adh); cudaGetSymbolAddress((void**)&adl, g_adl);
    cudaGetSymbolAddress((void**)&auh, g_auh); cudaGetSymbolAddress((void**)&aul, g_aul);
    cudaGetSymbolAddress((void**)&azh, g_azh); cudaGetSymbolAddress((void**)&azl, g_azl);

    cudaFuncSetAttribute(attn_mma, cudaFuncAttributeMaxDynamicSharedMemorySize, AT_SMEM);
    cudaFuncSetAttribute(gemm_mma, cudaFuncAttributeMaxDynamicSharedMemorySize, GMMA_SMEM);

    const dim3 blk(256);
    const dim3 gA(16, 16, 4);

    // ---- prep ----
    rmsnorm_k<<<B_*L_, blk>>>(inputs, ln1, xnh, xnl);
    {
        SplitJobs J;
        const float* srcs[NSEG] = { sa_wq, sa_wk, sa_wv, sa_wo, ca_wq, ca_wk, ca_wv, ca_wo,
                                    wi0, wi1, mwo, encoded };
        __nv_bfloat16* dhs[NSEG] = { wqkvh, wqkvh, wqkvh, woh, cqh, ckvh, ckvh, coh,
                                     w01h, w01h, wmh, ench };
        __nv_bfloat16* dls[NSEG] = { wqkvl, wqkvl, wqkvl, wol, cql, ckvl, ckvl, col_,
                                     w01l, w01l, wml, encl };
        int sizes[NSEG]   = { D_*D_, D_*D_, D_*D_, D_*D_, D_*D_, D_*D_, D_*D_, D_*D_,
                              D_*F_, D_*F_, F_*D_, B_*L_*D_ };
        int rowlen[NSEG]  = { 1024, 1024, 1024, 1024, 1024, 1024, 1024, 1024,
                              F_, F_, 1024, 1024 };
        int dstride[NSEG] = { 3072, 3072, 3072, 1024, 1024, 2048, 2048, 1024,
                              5632, 5632, 1024, 1024 };
        int cmul[NSEG]    = { 1, 1, 1, 1, 1, 1, 1, 1, 2, 2, 1, 1 };
        int coff[NSEG]    = { 0, 1024, 2048, 0, 0, 0, 1024, 0, 0, 1, 0, 0 };
        int acc = 0;
        for (int i = 0; i < NSEG; i++) {
            J.src[i] = srcs[i]; J.dh[i] = dhs[i]; J.dl[i] = dls[i];
            J.row_len[i] = rowlen[i]; J.dst_stride[i] = dstride[i];
            J.col_mul[i] = cmul[i]; J.col_off[i] = coff[i];
            acc += sizes[i] / 1024;
            J.blk_end[i] = acc;
        }
        wsplit_all<<<acc, blk>>>(J);
    }
    adprep<<<(B_*D_*64 + B_*A_*D_/2 + 255)/256, blk>>>(awd, awu, adh, adl, auh, aul);

    // ---- self attention ----
    gemm_mma<<<dim3(24, 32), blk, GMMA_SMEM>>>(xnh, xnl, wqkvh, wqkvl, nullptr, nullptr,
                                               nullptr, nullptr, D_, 3072, 6, 1.0f, 0, 0, 0, nullptr);
    prefix_k<<<(B_*P_*H_*HD_ + 255)/256, blk>>>(pk, pv, 0, kh, kl, vh, vl);
    attn_mma<<<gA, blk, AT_SMEM>>>(qh, ql, kh, kl, vh, vl, relpos, aoh, aol, 1, 1);
    gemm_mma<<<dim3(8, 32), blk, GMMA_SMEM>>>(aoh, aol, woh, wol, x1, inputs,
                                              nullptr, nullptr, D_, D_, 0, 1.0f, 0, 0, 0, nullptr);

    // ---- cross attention ----
    rmsnorm_k<<<B_*L_, blk>>>(x1, ln2, xnh, xnl);
    prefix_k<<<(B_*P_*H_*HD_ + 255)/256, blk>>>(pk, pv, 1, kh, kl, vh, vl);
    gemm_mma<<<dim3(8, 32), blk, GMMA_SMEM>>>(xnh, xnl, cqh, cql, nullptr, nullptr,
                                              qh, ql, D_, D_, 2, 0.125f, 0, 0, 0, nullptr);
    gemm_mma<<<dim3(16, 32), blk, GMMA_SMEM>>>(ench, encl, ckvh, ckvl, nullptr, nullptr,
                                               nullptr, nullptr, D_, 2048, 7, 1.0f, 0, 0, 0, nullptr);
    attn_mma<<<gA, blk, AT_SMEM>>>(qh, ql, kh, kl, vh, vl, relpos, aoh, aol, 0, 0);
    gemm_mma<<<dim3(8, 32), blk, GMMA_SMEM>>>(aoh, aol, coh, col_, y, x1,
                                              nullptr, nullptr, D_, D_, 0, 1.0f, 0, 0, 0, nullptr);

    // ---- MLP (fused gated) + adapter ----
    rmsnorm_k<<<B_*L_, blk>>>(y, ln3, xnh, xnl);
    gemm_mma<<<dim3(44, 32), blk, GMMA_SMEM>>>(xnh, xnl, w01h, w01l, nullptr, nullptr,
                                               gh, gl, D_, 5632, 8, 1.0f, 0, 0, 0, nullptr);
    gemm_mma<<<dim3(8, 32), blk, GMMA_SMEM>>>(gh, gl, wmh, wml, out, y,
                                              nullptr, nullptr, F_, D_, 0, 1.0f, 0, 0, 0, nullptr);
    gemm_mma<<<dim3(1, 8, 4), blk, GMMA_SMEM>>>(xnh, xnl, adh, adl, nullptr, nullptr, azh, azl,
                                                D_, 128, 4, 1.0f,
                                                (size_t)L_*D_, (size_t)D_*128, (size_t)L_*A_, abd);
    gemm_mma<<<dim3(8, 8, 4), blk, GMMA_SMEM>>>(azh, azl, auh, aul, out, nullptr, nullptr, nullptr,
                                                A_, D_, 5, 1.0f,
                                                (size_t)L_*A_, (size_t)A_*D_, (size_t)L_*D_, abu);
}

// round 15
// speedup vs baseline: 1.1206x; 1.1206x over previous
#include <cuda_runtime.h>
#include <cuda_bf16.h>
#include <cstdint>
#include <math.h>

#define B_ 4
#define L_ 1024
#define D_ 1024
#define H_ 16
#define HD_ 64
#define F_ 2816
#define A_ 64
#define P_ 30
#define LP_ 1054
#define LPP 1088
#define NT_ 17

// ---------------- scratch ----------------
__device__ float g_x1[B_*L_*D_];
__device__ float g_y [B_*L_*D_];
__device__ float g_h0[B_*L_*F_];
__device__ float g_h1[B_*L_*F_];

__device__ __nv_bfloat16 g_xnh[B_*L_*D_], g_xnl[B_*L_*D_];
__device__ __nv_bfloat16 g_ench[B_*L_*D_], g_encl[B_*L_*D_];
__device__ __nv_bfloat16 g_aoh[B_*L_*D_], g_aol[B_*L_*D_];
__device__ __nv_bfloat16 g_gh[B_*L_*F_], g_gl[B_*L_*F_];

__device__ __nv_bfloat16 g_qh[B_*H_*L_*HD_],  g_ql[B_*H_*L_*HD_];
__device__ __nv_bfloat16 g_kh[B_*H_*LPP*HD_], g_kl[B_*H_*LPP*HD_];
__device__ __nv_bfloat16 g_vh[B_*H_*LPP*HD_], g_vl[B_*H_*LPP*HD_];

__device__ __nv_bfloat16 g_wqh[D_*D_], g_wql[D_*D_];
__device__ __nv_bfloat16 g_wkh[D_*D_], g_wkl[D_*D_];
__device__ __nv_bfloat16 g_wvh[D_*D_], g_wvl[D_*D_];
__device__ __nv_bfloat16 g_woh[D_*D_], g_wol[D_*D_];
__device__ __nv_bfloat16 g_cqh[D_*D_], g_cql[D_*D_];
__device__ __nv_bfloat16 g_ckh[D_*D_], g_ckl[D_*D_];
__device__ __nv_bfloat16 g_cvh[D_*D_], g_cvl[D_*D_];
__device__ __nv_bfloat16 g_coh[D_*D_], g_col[D_*D_];
__device__ __nv_bfloat16 g_w0h[D_*F_], g_w0l[D_*F_];
__device__ __nv_bfloat16 g_w1h[D_*F_], g_w1l[D_*F_];
__device__ __nv_bfloat16 g_wmh[F_*D_], g_wml[F_*D_];

__device__ __nv_bfloat16 g_adh[B_*D_*128], g_adl[B_*D_*128];
__device__ __nv_bfloat16 g_auh[B_*A_*D_], g_aul[B_*A_*D_];
__device__ __nv_bfloat16 g_azh[B_*L_*A_], g_azl[B_*L_*A_];

__device__ __forceinline__ float gelu_f(float x) {
    float x3 = x*x*x;
    return 0.5f*x*(1.0f + tanhf(0.7978845608028654f*(x + 0.044715f*x3)));
}
__device__ __forceinline__ uint32_t smem_u32(const void* p) {
    uint32_t a;
    asm("{ .reg .u64 t; cvta.to.shared.u64 t, %1; cvt.u32.u64 %0, t; }" : "=r"(a) : "l"(p));
    return a;
}
__device__ __forceinline__ void mma16816(float* d, const uint32_t* a, const uint32_t* b) {
    asm volatile("mma.sync.aligned.m16n8k16.row.col.f32.bf16.bf16.f32 "
        "{%0,%1,%2,%3}, {%4,%5,%6,%7}, {%8,%9}, {%0,%1,%2,%3};"
        : "+f"(d[0]), "+f"(d[1]), "+f"(d[2]), "+f"(d[3])
        : "r"(a[0]), "r"(a[1]), "r"(a[2]), "r"(a[3]), "r"(b[0]), "r"(b[1]));
}
__device__ __forceinline__ void ldsm4(uint32_t* r, uint32_t addr) {
    asm volatile("ldmatrix.sync.aligned.m8n8.x4.shared.b16 {%0,%1,%2,%3}, [%4];"
        : "=r"(r[0]), "=r"(r[1]), "=r"(r[2]), "=r"(r[3]) : "r"(addr));
}
__device__ __forceinline__ void ldsm4t(uint32_t* r, uint32_t addr) {
    asm volatile("ldmatrix.sync.aligned.m8n8.x4.trans.shared.b16 {%0,%1,%2,%3}, [%4];"
        : "=r"(r[0]), "=r"(r[1]), "=r"(r[2]), "=r"(r[3]) : "r"(addr));
}
__device__ __forceinline__ void cp16(uint32_t dst, const void* src) {
    asm volatile("cp.async.cg.shared.global [%0], [%1], 16;"
        :: "r"(dst), "l"(__cvta_generic_to_global(src)));
}
#define CP_COMMIT() asm volatile("cp.async.commit_group;" ::: "memory")
#define CP_WAIT0()  asm volatile("cp.async.wait_group 0;" ::: "memory")
#define CP_WAIT1()  asm volatile("cp.async.wait_group 1;" ::: "memory")

__device__ __forceinline__ void split_bf16(float x, __nv_bfloat16& h, __nv_bfloat16& l) {
    h = __float2bfloat16(x);
    l = __float2bfloat16(x - __bfloat162float(h));
}
__device__ __forceinline__ uint32_t packbf2(__nv_bfloat16 a, __nv_bfloat16 b) {
    __nv_bfloat162 t; t.x = a; t.y = b;
    return *(uint32_t*)&t;
}

// ---------------- rmsnorm -> bf16 planes ----------------
__global__ void __launch_bounds__(256) rmsnorm_k(const float* __restrict__ x,
                                                 const float* __restrict__ sc,
                                                 __nv_bfloat16* __restrict__ oh,
                                                 __nv_bfloat16* __restrict__ ol) {
    __shared__ float red[8];
    int row = blockIdx.x;
    const float* xr = x + (size_t)row * D_;
    float4 v = *(const float4*)(xr + threadIdx.x*4);
    float ss = v.x*v.x + v.y*v.y + v.z*v.z + v.w*v.w;
    #pragma unroll
    for (int off = 16; off; off >>= 1) ss += __shfl_xor_sync(0xffffffffu, ss, off);
    if ((threadIdx.x & 31) == 0) red[threadIdx.x >> 5] = ss;
    __syncthreads();
    if (threadIdx.x < 8) {
        float t = red[threadIdx.x];
        #pragma unroll
        for (int off = 4; off; off >>= 1) t += __shfl_xor_sync(0xffu, t, off);
        if (threadIdx.x == 0) red[0] = t;
    }
    __syncthreads();
    float rms = rsqrtf(red[0] * (1.0f / D_) + 1e-6f);
    float4 s4 = *(const float4*)(sc + threadIdx.x*4);
    float r0 = v.x*rms*s4.x, r1 = v.y*rms*s4.y, r2 = v.z*rms*s4.z, r3 = v.w*rms*s4.w;
    size_t base = (size_t)row * D_ + threadIdx.x*4;
    __nv_bfloat16 h0, l0, h1, l1, h2, l2, h3, l3;
    split_bf16(r0, h0, l0); split_bf16(r1, h1, l1);
    split_bf16(r2, h2, l2); split_bf16(r3, h3, l3);
    *(uint32_t*)(oh + base) = packbf2(h0, h1);
    *(uint32_t*)(oh + base + 2) = packbf2(h2, h3);
    *(uint32_t*)(ol + base) = packbf2(l0, l1);
    *(uint32_t*)(ol + base + 2) = packbf2(l2, l3);
}

// ---------------- fused multi-tensor split ----------------
#define NSEG 12
struct SplitJobs {
    const float* src[NSEG];
    __nv_bfloat16* dh[NSEG];
    __nv_bfloat16* dl[NSEG];
    int blk_end[NSEG];
};

__global__ void __launch_bounds__(256) wsplit_all(SplitJobs J) {
    int bid = blockIdx.x;
    int seg = 0;
    #pragma unroll
    for (int s = 0; s < NSEG; s++) { if (bid >= J.blk_end[s]) seg = s + 1; }
    int base = seg ? J.blk_end[seg-1] : 0;
    size_t i = (((size_t)(bid - base))*256 + threadIdx.x) * 4;
    float4 v = *(const float4*)(J.src[seg] + i);
    __nv_bfloat16 h0, l0, h1, l1, h2, l2, h3, l3;
    split_bf16(v.x, h0, l0); split_bf16(v.y, h1, l1);
    split_bf16(v.z, h2, l2); split_bf16(v.w, h3, l3);
    __nv_bfloat16* dh = J.dh[seg];
    __nv_bfloat16* dl = J.dl[seg];
    *(uint32_t*)(dh + i) = packbf2(h0, h1);
    *(uint32_t*)(dh + i + 2) = packbf2(h2, h3);
    *(uint32_t*)(dl + i) = packbf2(l0, l1);
    *(uint32_t*)(dl + i + 2) = packbf2(l2, l3);
}

// ---------------- adapter weight prep ----------------
__global__ void __launch_bounds__(256) adprep(const float* __restrict__ awd,
                                              const float* __restrict__ awu,
                                              __nv_bfloat16* __restrict__ adh,
                                              __nv_bfloat16* __restrict__ adl,
                                              __nv_bfloat16* __restrict__ auh,
                                              __nv_bfloat16* __restrict__ aul) {
    int idx = blockIdx.x*256 + threadIdx.x;
    const int NPAD = B_*D_*64;
    if (idx < NPAD) {
        int pa = idx & 63;
        int row = idx >> 6;
        uint32_t vh = 0, vl = 0;
        if (pa < 32) {
            float2 v = *(const float2*)(awd + (size_t)row*A_ + pa*2);
            __nv_bfloat16 h0, l0, h1, l1;
            split_bf16(v.x, h0, l0); split_bf16(v.y, h1, l1);
            vh = packbf2(h0, h1); vl = packbf2(l0, l1);
        }
        *(uint32_t*)(adh + (size_t)row*128 + pa*2) = vh;
        *(uint32_t*)(adl + (size_t)row*128 + pa*2) = vl;
    } else {
        int j = idx - NPAD;
        if (j < B_*A_*D_/2) {
            float2 v = *(const float2*)(awu + (size_t)j*2);
            __nv_bfloat16 h0, l0, h1, l1;
            split_bf16(v.x, h0, l0); split_bf16(v.y, h1, l1);
            *(uint32_t*)(auh + (size_t)j*2) = packbf2(h0, h1);
            *(uint32_t*)(aul + (size_t)j*2) = packbf2(l0, l1);
        }
    }
}

// ---------------- prefix KV copy ----------------
__global__ void __launch_bounds__(256) prefix_k(const float* __restrict__ pk,
                                                const float* __restrict__ pv,
                                                int sel,
                                                __nv_bfloat16* __restrict__ kh,
                                                __nv_bfloat16* __restrict__ kl,
                                                __nv_bfloat16* __restrict__ vh,
                                                __nv_bfloat16* __restrict__ vl) {
    int idx = blockIdx.x*256 + threadIdx.x;
    if (idx >= B_*P_*H_*HD_) return;
    int b = idx / (P_*H_*HD_);
    int rem = idx % (P_*H_*HD_);
    int p = rem >> 10;
    int h = (rem >> 6) & 15;
    int e = rem & 63;
    size_t src = (((size_t)(b*2 + sel)*P_ + p)*H_ + h)*HD_ + e;
    size_t dst = (((size_t)(b*H_ + h))*LPP + p)*HD_ + e;
    __nv_bfloat16 hh, ll;
    split_bf16(pk[src], hh, ll);
    kh[dst] = hh; kl[dst] = ll;
    split_bf16(pv[src], hh, ll);
    vh[dst] = hh; vl[dst] = ll;
}

// ---------------- gated gelu -> hi/lo planes ----------------
__global__ void __launch_bounds__(256) gated_k(const float* __restrict__ h0,
                                               const float* __restrict__ h1,
                                               __nv_bfloat16* __restrict__ gh,
                                               __nv_bfloat16* __restrict__ gl) {
    size_t i = ((size_t)blockIdx.x*256 + threadIdx.x) * 4;
    float4 a = *(const float4*)(h0 + i);
    float4 b = *(const float4*)(h1 + i);
    a.x = gelu_f(a.x)*b.x; a.y = gelu_f(a.y)*b.y;
    a.z = gelu_f(a.z)*b.z; a.w = gelu_f(a.w)*b.w;
    __nv_bfloat16 p0, q0, p1, q1, p2, q2, p3, q3;
    split_bf16(a.x, p0, q0); split_bf16(a.y, p1, q1);
    split_bf16(a.z, p2, q2); split_bf16(a.w, p3, q3);
    *(uint32_t*)(gh + i) = packbf2(p0, p1);
    *(uint32_t*)(gh + i + 2) = packbf2(p2, p3);
    *(uint32_t*)(gl + i) = packbf2(q0, q1);
    *(uint32_t*)(gl + i + 2) = packbf2(q2, q3);
}

// ============== mma.sync bf16-split GEMM, tile 128x64, 2 CTA/SM ==============
// modes: 0 = fp32 C (+R); 2 = Q planes; 3 = KV planes; 4 = adapter down; 5 = adapter up
// smem/stage: A 2x16KB + B 2x8KB = 48KB; double buffered = 96KB
#define GMMA_SMEM (2*49152)

__device__ __forceinline__ void g_load_stage(
    uint32_t base, int tid, int m0, int n0, int k0, int K, int N,
    const __nv_bfloat16* Ah, const __nv_bfloat16* Al,
    const __nv_bfloat16* Bh, const __nv_bfloat16* Bl)
{
    #pragma unroll
    for (int pl = 0; pl < 2; pl++) {
        const __nv_bfloat16* Ap = pl ? Al : Ah;
        uint32_t ab = base + pl*16384;
        #pragma unroll
        for (int i = 0; i < 4; i++) {
            int idx = tid + i*256;
            int row = idx >> 3, c = idx & 7;
            uint32_t dst = ab + row*128 + ((c ^ (row & 7)) << 4);
            cp16(dst, Ap + (size_t)(m0 + row)*K + k0 + c*8);
        }
        const __nv_bfloat16* Bp = pl ? Bl : Bh;
        uint32_t bb = base + 32768 + pl*8192;
        #pragma unroll
        for (int i = 0; i < 2; i++) {
            int idx = tid + i*256;
            int row = idx >> 3, c = idx & 7;       // row = k 0..63, c = n-chunk 0..7
            uint32_t dst = bb + row*128 + ((c ^ (row & 7)) << 4);
            cp16(dst, Bp + (size_t)(k0 + row)*N + n0 + c*8);
        }
    }
}

__global__ void __launch_bounds__(256, 2) gemm_mma(
    const __nv_bfloat16* __restrict__ Ah, const __nv_bfloat16* __restrict__ Al,
    const __nv_bfloat16* __restrict__ Bh, const __nv_bfloat16* __restrict__ Bl,
    float* __restrict__ C, const float* __restrict__ R,
    __nv_bfloat16* __restrict__ Ch, __nv_bfloat16* __restrict__ Cl,
    int K, int N, int mode, float scale,
    size_t bsA, size_t bsB, size_t bsC, const float* __restrict__ bias)
{
    extern __shared__ __align__(1024) char smem[];
    uint32_t sb = smem_u32(smem);
    const int tid = threadIdx.x;
    const int wid = tid >> 5, lane = tid & 31;
    const int warp_m = wid & 3, warp_n = wid >> 2;   // 4 x 2
    const int m0 = blockIdx.y*128, n0 = blockIdx.x*64;
    const size_t z = blockIdx.z;
    Ah += z*bsA; Al += z*bsA;
    Bh += z*bsB; Bl += z*bsB;

    float acc[8][4] = {};   // [mt*4 + nt][4]  (warp tile 32x32)

    const int S = K >> 6;
    g_load_stage(sb, tid, m0, n0, 0, K, N, Ah, Al, Bh, Bl);
    CP_COMMIT();

    for (int s = 0; s < S; s++) {
        if (s + 1 < S) {
            g_load_stage(sb + ((s+1)&1)*49152, tid, m0, n0, (s+1)*64, K, N, Ah, Al, Bh, Bl);
            CP_COMMIT();
            CP_WAIT1();
        } else {
            CP_WAIT0();
        }
        __syncthreads();
        uint32_t base = sb + (s&1)*49152;

        #pragma unroll
        for (int c16 = 0; c16 < 4; c16++) {
            uint32_t ah[2][4], al[2][4];
            #pragma unroll
            for (int mt = 0; mt < 2; mt++) {
                int r = warp_m*32 + mt*16 + (lane & 15);
                int colc = c16*2 + (lane >> 4);
                uint32_t a = base + r*128 + (((uint32_t)(colc ^ (r & 7))) << 4);
                ldsm4(ah[mt], a);
                ldsm4(al[mt], a + 16384);
            }
            uint32_t bh[4][2], bl[4][2];
            #pragma unroll
            for (int j = 0; j < 2; j++) {
                int kr = c16*16 + (lane & 15);
                int chunk = warp_n*4 + j*2 + (lane >> 4);     // 0..7
                uint32_t cc = (uint32_t)(chunk ^ (kr & 7));
                uint32_t addr = base + 32768 + kr*128 + (cc << 4);
                uint32_t t[4];
                ldsm4t(t, addr);
                bh[2*j][0] = t[0]; bh[2*j][1] = t[1];
                bh[2*j+1][0] = t[2]; bh[2*j+1][1] = t[3];
                ldsm4t(t, addr + 8192);
                bl[2*j][0] = t[0]; bl[2*j][1] = t[1];
                bl[2*j+1][0] = t[2]; bl[2*j+1][1] = t[3];
            }
            #pragma unroll
            for (int mt = 0; mt < 2; mt++) {
                #pragma unroll
                for (int nt = 0; nt < 4; nt++) {
                    float* d = acc[mt*4 + nt];
                    mma16816(d, ah[mt], bh[nt]);
                    mma16816(d, al[mt], bh[nt]);
                    mma16816(d, ah[mt], bl[nt]);
                }
            }
        }
        __syncthreads();
    }

    // epilogue
    #pragma unroll
    for (int mt = 0; mt < 2; mt++) {
        #pragma unroll
        for (int nt = 0; nt < 4; nt++) {
            float* a4 = acc[mt*4 + nt];
            int r = m0 + warp_m*32 + mt*16 + (lane >> 2);
            int col = n0 + warp_n*32 + nt*8 + (lane & 3)*2;
            #pragma unroll
            for (int half = 0; half < 2; half++) {
                int rr = r + half*8;
                float2 v = make_float2(a4[half*2]*scale, a4[half*2 + 1]*scale);
                if (mode == 0) {
                    size_t off = (size_t)rr*N + col;
                    if (R) { v.x += R[off]; v.y += R[off + 1]; }
                    *(float2*)(C + off) = v;
                } else if (mode == 2 || mode == 3) {
                    int b = rr >> 10, l = rr & 1023;
                    int hh = col >> 6, e = col & 63;
                    size_t bo = (mode == 2)
                        ? (((size_t)(b*H_ + hh))*1024 + l)*64 + e
                        : (((size_t)(b*H_ + hh))*LPP + l + P_)*64 + e;
                    __nv_bfloat16 h0, l0, h1, l1;
                    split_bf16(v.x, h0, l0); split_bf16(v.y, h1, l1);
                    *(uint32_t*)(Ch + bo) = packbf2(h0, h1);
                    *(uint32_t*)(Cl + bo) = packbf2(l0, l1);
                } else if (mode == 4) {
                    if (col < 64) {
                        const float* bd = bias + z*A_;
                        v.x = gelu_f(v.x + bd[col]);
                        v.y = gelu_f(v.y + bd[col + 1]);
                        __nv_bfloat16 h0, l0, h1, l1;
                        split_bf16(v.x, h0, l0); split_bf16(v.y, h1, l1);
                        size_t bo = z*bsC + (size_t)rr*64 + col;
                        *(uint32_t*)(Ch + bo) = packbf2(h0, h1);
                        *(uint32_t*)(Cl + bo) = packbf2(l0, l1);
                    }
                } else {  // mode 5
                    const float* bu = bias + z*D_;
                    size_t off = z*bsC + (size_t)rr*N + col;
                    float2 cc = *(float2*)(C + off);
                    cc.x += v.x + bu[col];
                    cc.y += v.y + bu[col + 1];
                    *(float2*)(C + off) = cc;
                }
            }
        }
    }
}

// ================= mma.sync flash attention =================
#define AT_SMEM 87296

__global__ void __launch_bounds__(256) attn_mma(
    const __nv_bfloat16* __restrict__ Qhp, const __nv_bfloat16* __restrict__ Qlp,
    const __nv_bfloat16* __restrict__ Khp, const __nv_bfloat16* __restrict__ Klp,
    const __nv_bfloat16* __restrict__ Vhp, const __nv_bfloat16* __restrict__ Vlp,
    const float* __restrict__ relpos,
    __nv_bfloat16* __restrict__ Oh, __nv_bfloat16* __restrict__ Ol,
    int causal, int use_bias)
{
    extern __shared__ __align__(1024) char sm[];
    uint32_t sb = smem_u32(sm);
    const uint32_t sQ = sb;
    const uint32_t sStage = sb + 16384;
    float* bv   = (float*)(sm + 81920);
    float* wmax = (float*)(sm + 86272);
    float* wsum = (float*)(sm + 86784);

    const int tid = threadIdx.x;
    const int lane = tid & 31, wid = tid >> 5;
    const int warp_m = wid & 3, warp_n = wid >> 2;
    const int q0 = blockIdx.x*64, h = blockIdx.y, b = blockIdx.z;
    const int bh = b*H_ + h;
    const int r0 = lane >> 2;

    {
        const __nv_bfloat16* qg  = Qhp + ((size_t)bh*L_ + q0)*64;
        const __nv_bfloat16* qg2 = Qlp + ((size_t)bh*L_ + q0)*64;
        #pragma unroll
        for (int i = 0; i < 2; i++) {
            int idx = tid + i*256;
            int row = idx >> 3, c = idx & 7;
            uint32_t sw = row*128 + ((c ^ (row & 7)) << 4);
            cp16(sQ + sw, qg + row*64 + c*8);
            cp16(sQ + 8192 + sw, qg2 + row*64 + c*8);
        }
    }
    if (use_bias) {
        for (int d = tid; d < LPP; d += 256) {
            int bb;
            if (d < 16) bb = d;
            else {
                float t = logf((float)d / 16.0f) / 2.0794415416798357f * 16.0f;
                bb = 16 + (int)t;
                if (bb > 31) bb = 31;
            }
            bv[d] = relpos[h*32 + bb];
        }
    }

    const size_t kvbase = (size_t)bh * LPP * 64;
    const __nv_bfloat16* Kh = Khp + kvbase;
    const __nv_bfloat16* Kl = Klp + kvbase;
    const __nv_bfloat16* Vh = Vhp + kvbase;
    const __nv_bfloat16* Vl = Vlp + kvbase;

    int nk = NT_;
    if (causal) { int t = (q0 + 63 + P_)/64 + 1; if (t < nk) nk = t; }

    {
        uint32_t base = sStage;
        const __nv_bfloat16* ptrs[4] = { Kh, Kl, Vh, Vl };
        #pragma unroll
        for (int pl = 0; pl < 4; pl++)
            #pragma unroll
            for (int i = 0; i < 2; i++) {
                int idx = tid + i*256;
                int row = idx >> 3, c = idx & 7;
                uint32_t sw = row*128 + ((c ^ (row & 7)) << 4);
                cp16(base + pl*8192 + sw, ptrs[pl] + (size_t)row*64 + c*8);
            }
    }
    CP_COMMIT();

    float m_run[2] = {-1e30f, -1e30f};
    float l_run[2] = {0.0f, 0.0f};
    float oacc[8][4] = {};

    for (int s = 0; s < nk; s++) {
        if (s + 1 < nk) {
            uint32_t base = sStage + ((s+1)&1)*32768;
            const __nv_bfloat16* ptrs[4] = { Kh, Kl, Vh, Vl };
            #pragma unroll
            for (int pl = 0; pl < 4; pl++)
                #pragma unroll
                for (int i = 0; i < 2; i++) {
                    int idx = tid + i*256;
                    int row = idx >> 3, c = idx & 7;
                    uint32_t sw = row*128 + ((c ^ (row & 7)) << 4);
                    cp16(base + pl*8192 + sw, ptrs[pl] + (size_t)((s+1)*64 + row)*64 + c*8);
                }
            CP_COMMIT();
            CP_WAIT1();
        } else {
            CP_WAIT0();
        }
        __syncthreads();
        uint32_t kbuf = sStage + (s&1)*32768;
        uint32_t vbuf = kbuf + 16384;

        float sacc[4][4] = {};
        #pragma unroll
        for (int kc = 0; kc < 4; kc++) {
            uint32_t qa[4], qla[4];
            {
                int row = warp_m*16 + (lane & 15);
                int chunk = 2*kc + (lane >> 4);
                uint32_t a = sQ + row*128 + (((uint32_t)(chunk ^ (row & 7))) << 4);
                ldsm4(qa, a);
                ldsm4(qla, a + 8192);
            }
            uint32_t kbh[4][2], kbl2[4][2];
            #pragma unroll
            for (int half = 0; half < 2; half++) {
                int g = lane >> 3, l8 = lane & 7;
                int nrow = warp_n*32 + half*16 + ((g & 2) ? 8 : 0) + l8;
                int chunk = 2*kc + (g & 1);
                uint32_t a = kbuf + nrow*128 + (((uint32_t)(chunk ^ (nrow & 7))) << 4);
                uint32_t t[4];
                ldsm4(t, a);
                kbh[half*2][0] = t[0]; kbh[half*2][1] = t[1];
                kbh[half*2+1][0] = t[2]; kbh[half*2+1][1] = t[3];
                ldsm4(t, a + 8192);
                kbl2[half*2][0] = t[0]; kbl2[half*2][1] = t[1];
                kbl2[half*2+1][0] = t[2]; kbl2[half*2+1][1] = t[3];
            }
            #pragma unroll
            for (int nt = 0; nt < 4; nt++) {
                mma16816(sacc[nt], qa, kbh[nt]);
                mma16816(sacc[nt], qla, kbh[nt]);
                mma16816(sacc[nt], qa, kbl2[nt]);
            }
        }

        const int kt64 = s*64;
        const int rbase = q0 + warp_m*16 + r0;
        #pragma unroll
        for (int nt = 0; nt < 4; nt++) {
            #pragma unroll
            for (int half = 0; half < 2; half++) {
                #pragma unroll
                for (int j = 0; j < 2; j++) {
                    int key = kt64 + warp_n*32 + nt*8 + (lane & 3)*2 + j;
                    float v = sacc[nt][half*2 + j];
                    if (key >= LP_) v = -1e10f;
                    else if (causal && key >= P_) {
                        int d = (rbase + half*8) - (key - P_);
                        if (d < 0) v = -1e10f;
                        else if (use_bias) v += bv[d];
                    }
                    sacc[nt][half*2 + j] = v;
                }
            }
        }

        float mx[2] = {-1e30f, -1e30f};
        #pragma unroll
        for (int nt = 0; nt < 4; nt++) {
            mx[0] = fmaxf(mx[0], fmaxf(sacc[nt][0], sacc[nt][1]));
            mx[1] = fmaxf(mx[1], fmaxf(sacc[nt][2], sacc[nt][3]));
        }
        mx[0] = fmaxf(mx[0], __shfl_xor_sync(0xffffffffu, mx[0], 1));
        mx[0] = fmaxf(mx[0], __shfl_xor_sync(0xffffffffu, mx[0], 2));
        mx[1] = fmaxf(mx[1], __shfl_xor_sync(0xffffffffu, mx[1], 1));
        mx[1] = fmaxf(mx[1], __shfl_xor_sync(0xffffffffu, mx[1], 2));
        if ((lane & 3) == 0) {
            wmax[warp_n*64 + warp_m*16 + r0] = mx[0];
            wmax[warp_n*64 + warp_m*16 + r0 + 8] = mx[1];
        }
        __syncthreads();
        float mn[2], corr[2];
        #pragma unroll
        for (int half = 0; half < 2; half++) {
            int rr = warp_m*16 + r0 + half*8;
            float mt = fmaxf(wmax[rr], wmax[64 + rr]);
            mn[half] = fmaxf(m_run[half], mt);
            corr[half] = __expf(m_run[half] - mn[half]);
        }
        float rs[2] = {0.0f, 0.0f};
        #pragma unroll
        for (int nt = 0; nt < 4; nt++) {
            #pragma unroll
            for (int half = 0; half < 2; half++) {
                #pragma unroll
                for (int j = 0; j < 2; j++) {
                    float p = __expf(sacc[nt][half*2 + j] - mn[half]);
                    sacc[nt][half*2 + j] = p;
                    rs[half] += p;
                }
            }
        }
        rs[0] += __shfl_xor_sync(0xffffffffu, rs[0], 1);
        rs[0] += __shfl_xor_sync(0xffffffffu, rs[0], 2);
        rs[1] += __shfl_xor_sync(0xffffffffu, rs[1], 1);
        rs[1] += __shfl_xor_sync(0xffffffffu, rs[1], 2);
        if ((lane & 3) == 0) {
            wsum[warp_n*64 + warp_m*16 + r0] = rs[0];
            wsum[warp_n*64 + warp_m*16 + r0 + 8] = rs[1];
        }
        __syncthreads();
        #pragma unroll
        for (int half = 0; half < 2; half++) {
            int rr = warp_m*16 + r0 + half*8;
            l_run[half] = l_run[half]*corr[half] + wsum[rr] + wsum[64 + rr];
            m_run[half] = mn[half];
        }

        #pragma unroll
        for (int nt = 0; nt < 8; nt++) {
            oacc[nt][0] *= corr[0]; oacc[nt][1] *= corr[0];
            oacc[nt][2] *= corr[1]; oacc[nt][3] *= corr[1];
        }

        #pragma unroll
        for (int kc2 = 0; kc2 < 2; kc2++) {
            uint32_t pah[4], pal[4];
            {
                __nv_bfloat16 h0, l0, h1, l1;
                split_bf16(sacc[2*kc2][0], h0, l0); split_bf16(sacc[2*kc2][1], h1, l1);
                pah[0] = packbf2(h0, h1); pal[0] = packbf2(l0, l1);
                split_bf16(sacc[2*kc2][2], h0, l0); split_bf16(sacc[2*kc2][3], h1, l1);
                pah[1] = packbf2(h0, h1); pal[1] = packbf2(l0, l1);
                split_bf16(sacc[2*kc2+1][0], h0, l0); split_bf16(sacc[2*kc2+1][1], h1, l1);
                pah[2] = packbf2(h0, h1); pal[2] = packbf2(l0, l1);
                split_bf16(sacc[2*kc2+1][2], h0, l0); split_bf16(sacc[2*kc2+1][3], h1, l1);
                pah[3] = packbf2(h0, h1); pal[3] = packbf2(l0, l1);
            }
            uint32_t vbh[8][2], vbl[8][2];
            #pragma unroll
            for (int eg = 0; eg < 4; eg++) {
                int kr = warp_n*32 + kc2*16 + (lane & 15);
                int chunk = 2*eg + (lane >> 4);
                uint32_t a = vbuf + kr*128 + (((uint32_t)(chunk ^ (kr & 7))) << 4);
                uint32_t t[4];
                ldsm4t(t, a);
                vbh[eg*2][0] = t[0]; vbh[eg*2][1] = t[1];
                vbh[eg*2+1][0] = t[2]; vbh[eg*2+1][1] = t[3];
                ldsm4t(t, a + 8192);
                vbl[eg*2][0] = t[0]; vbl[eg*2][1] = t[1];
                vbl[eg*2+1][0] = t[2]; vbl[eg*2+1][1] = t[3];
            }
            #pragma unroll
            for (int nt = 0; nt < 8; nt++) {
                mma16816(oacc[nt], pah, vbh[nt]);
                mma16816(oacc[nt], pal, vbh[nt]);
                mma16816(oacc[nt], pah, vbl[nt]);
            }
        }
        __syncthreads();
    }

    float inv[2] = {1.0f / l_run[0], 1.0f / l_run[1]};
    float* ocomb = (float*)(sm + 16384);
    if (warp_n == 1) {
        #pragma unroll
        for (int nt = 0; nt < 8; nt++) {
            #pragma unroll
            for (int half = 0; half < 2; half++) {
                int row = warp_m*16 + r0 + half*8;
                int col = nt*8 + (lane & 3)*2;
                *(float2*)(ocomb + row*64 + col) =
                    make_float2(oacc[nt][half*2], oacc[nt][half*2 + 1]);
            }
        }
    }
    __syncthreads();
    if (warp_n == 0) {
        #pragma unroll
        for (int nt = 0; nt < 8; nt++) {
            #pragma unroll
            for (int half = 0; half < 2; half++) {
                int row = warp_m*16 + r0 + half*8;
                int col = nt*8 + (lane & 3)*2;
                float2 o2 = *(float2*)(ocomb + row*64 + col);
                float v0 = (oacc[nt][half*2] + o2.x) * inv[half];
                float v1 = (oacc[nt][half*2 + 1] + o2.y) * inv[half];
                __nv_bfloat16 h0, l0, h1, l1;
                split_bf16(v0, h0, l0); split_bf16(v1, h1, l1);
                size_t base = (((size_t)(b*L_ + q0 + row))*H_ + h)*HD_ + col;
                *(uint32_t*)(Oh + base) = packbf2(h0, h1);
                *(uint32_t*)(Ol + base) = packbf2(l0, l1);
            }
        }
    }
}

// ---------------- host launcher ----------------
extern "C" void kernel_launch(void* const* d_in, const int* in_sizes, int n_in,
                              void* d_out, int out_size) {
    const float* inputs  = (const float*)d_in[0];
    const float* encoded = (const float*)d_in[1];
    const float* awd     = (const float*)d_in[2];
    const float* awu     = (const float*)d_in[3];
    const float* abd     = (const float*)d_in[4];
    const float* abu     = (const float*)d_in[5];
    const float* pk      = (const float*)d_in[6];
    const float* pv      = (const float*)d_in[7];
    const float* ln1     = (const float*)d_in[8];
    const float* ln2     = (const float*)d_in[9];
    const float* ln3     = (const float*)d_in[10];
    const float* sa_wq   = (const float*)d_in[11];
    const float* sa_wk   = (const float*)d_in[12];
    const float* sa_wv   = (const float*)d_in[13];
    const float* sa_wo   = (const float*)d_in[14];
    const float* ca_wq   = (const float*)d_in[15];
    const float* ca_wk   = (const float*)d_in[16];
    const float* ca_wv   = (const float*)d_in[17];
    const float* ca_wo   = (const float*)d_in[18];
    const float* relpos  = (const float*)d_in[19];
    const float* wi0     = (const float*)d_in[20];
    const float* wi1     = (const float*)d_in[21];
    const float* mwo     = (const float*)d_in[22];
    float* out = (float*)d_out;

    float *x1, *y, *h0, *h1;
    cudaGetSymbolAddress((void**)&x1, g_x1);
    cudaGetSymbolAddress((void**)&y,  g_y);
    cudaGetSymbolAddress((void**)&h0, g_h0);
    cudaGetSymbolAddress((void**)&h1, g_h1);

    __nv_bfloat16 *xnh, *xnl, *ench, *encl, *aoh, *aol, *gh, *gl;
    __nv_bfloat16 *qh, *ql, *kh, *kl, *vh, *vl;
    cudaGetSymbolAddress((void**)&xnh, g_xnh); cudaGetSymbolAddress((void**)&xnl, g_xnl);
    cudaGetSymbolAddress((void**)&ench, g_ench); cudaGetSymbolAddress((void**)&encl, g_encl);
    cudaGetSymbolAddress((void**)&aoh, g_aoh); cudaGetSymbolAddress((void**)&aol, g_aol);
    cudaGetSymbolAddress((void**)&gh, g_gh); cudaGetSymbolAddress((void**)&gl, g_gl);
    cudaGetSymbolAddress((void**)&qh, g_qh); cudaGetSymbolAddress((void**)&ql, g_ql);
    cudaGetSymbolAddress((void**)&kh, g_kh); cudaGetSymbolAddress((void**)&kl, g_kl);
    cudaGetSymbolAddress((void**)&vh, g_vh); cudaGetSymbolAddress((void**)&vl, g_vl);

    __nv_bfloat16 *wqh,*wql,*wkh,*wkl,*wvh,*wvl,*woh,*wol;
    __nv_bfloat16 *cqh,*cql,*ckh,*ckl,*cvh,*cvl,*coh,*col_;
    __nv_bfloat16 *w0h,*w0l,*w1h,*w1l,*wmh,*wml;
    __nv_bfloat16 *adh,*adl,*auh,*aul,*azh,*azl;
    cudaGetSymbolAddress((void**)&wqh, g_wqh); cudaGetSymbolAddress((void**)&wql, g_wql);
    cudaGetSymbolAddress((void**)&wkh, g_wkh); cudaGetSymbolAddress((void**)&wkl, g_wkl);
    cudaGetSymbolAddress((void**)&wvh, g_wvh); cudaGetSymbolAddress((void**)&wvl, g_wvl);
    cudaGetSymbolAddress((void**)&woh, g_woh); cudaGetSymbolAddress((void**)&wol, g_wol);
    cudaGetSymbolAddress((void**)&cqh, g_cqh); cudaGetSymbolAddress((void**)&cql, g_cql);
    cudaGetSymbolAddress((void**)&ckh, g_ckh); cudaGetSymbolAddress((void**)&ckl, g_ckl);
    cudaGetSymbolAddress((void**)&cvh, g_cvh); cudaGetSymbolAddress((void**)&cvl, g_cvl);
    cudaGetSymbolAddress((void**)&coh, g_coh); cudaGetSymbolAddress((void**)&col_, g_col);
    cudaGetSymbolAddress((void**)&w0h, g_w0h); cudaGetSymbolAddress((void**)&w0l, g_w0l);
    cudaGetSymbolAddress((void**)&w1h, g_w1h); cudaGetSymbolAddress((void**)&w1l, g_w1l);
    cudaGetSymbolAddress((void**)&wmh, g_wmh); cudaGetSymbolAddress((void**)&wml, g_wml);
    cudaGetSymbolAddress((void**)&adh, g_adh); cudaGetSymbolAddress((void**)&adl, g_adl);
    cudaGetSymbolAddress((void**)&auh, g_auh); cudaGetSymbolAddress((void**)&aul, g_aul);
    cudaGetSymbolAddress((void**)&azh, g_azh); cudaGetSymbolAddress((void**)&azl, g_azl);

    cudaFuncSetAttribute(attn_mma, cudaFuncAttributeMaxDynamicSharedMemorySize, AT_SMEM);
    cudaFuncSetAttribute(gemm_mma, cudaFuncAttributeMaxDynamicSharedMemorySize, GMMA_SMEM);

    const dim3 blk(256);
    const dim3 gDD(16, 32);   // N=1024 with 64-wide tiles
    const dim3 gDF(44, 32);   // N=2816
    const dim3 gA(16, 16, 4);

    // ---- prep ----
    rmsnorm_k<<<B_*L_, blk>>>(inputs, ln1, xnh, xnl);
    {
        SplitJobs J;
        const float* srcs[NSEG] = { sa_wq, sa_wk, sa_wv, sa_wo, ca_wq, ca_wk, ca_wv, ca_wo,
                                    wi0, wi1, mwo, encoded };
        __nv_bfloat16* dhs[NSEG] = { wqh, wkh, wvh, woh, cqh, ckh, cvh, coh, w0h, w1h, wmh, ench };
        __nv_bfloat16* dls[NSEG] = { wql, wkl, wvl, wol, cql, ckl, cvl, col_, w0l, w1l, wml, encl };
        int sizes[NSEG] = { D_*D_, D_*D_, D_*D_, D_*D_, D_*D_, D_*D_, D_*D_, D_*D_,
                            D_*F_, D_*F_, F_*D_, B_*L_*D_ };
        int acc = 0;
        for (int i = 0; i < NSEG; i++) {
            J.src[i] = srcs[i]; J.dh[i] = dhs[i]; J.dl[i] = dls[i];
            acc += sizes[i] / 1024;
            J.blk_end[i] = acc;
        }
        wsplit_all<<<acc, blk>>>(J);
    }
    adprep<<<(B_*D_*64 + B_*A_*D_/2 + 255)/256, blk>>>(awd, awu, adh, adl, auh, aul);
    prefix_k<<<(B_*P_*H_*HD_ + 255)/256, blk>>>(pk, pv, 0, kh, kl, vh, vl);

    // ---- self attention ----
    gemm_mma<<<gDD, blk, GMMA_SMEM>>>(xnh, xnl, wqh, wql, nullptr, nullptr, qh, ql, D_, D_, 2, 0.125f, 0, 0, 0, nullptr);
    gemm_mma<<<gDD, blk, GMMA_SMEM>>>(xnh, xnl, wkh, wkl, nullptr, nullptr, kh, kl, D_, D_, 3, 1.0f, 0, 0, 0, nullptr);
    gemm_mma<<<gDD, blk, GMMA_SMEM>>>(xnh, xnl, wvh, wvl, nullptr, nullptr, vh, vl, D_, D_, 3, 1.0f, 0, 0, 0, nullptr);
    attn_mma<<<gA, blk, AT_SMEM>>>(qh, ql, kh, kl, vh, vl, relpos, aoh, aol, 1, 1);
    gemm_mma<<<gDD, blk, GMMA_SMEM>>>(aoh, aol, woh, wol, x1, inputs, nullptr, nullptr, D_, D_, 0, 1.0f, 0, 0, 0, nullptr);

    // ---- cross attention ----
    rmsnorm_k<<<B_*L_, blk>>>(x1, ln2, xnh, xnl);
    prefix_k<<<(B_*P_*H_*HD_ + 255)/256, blk>>>(pk, pv, 1, kh, kl, vh, vl);
    gemm_mma<<<gDD, blk, GMMA_SMEM>>>(xnh, xnl, cqh, cql, nullptr, nullptr, qh, ql, D_, D_, 2, 0.125f, 0, 0, 0, nullptr);
    gemm_mma<<<gDD, blk, GMMA_SMEM>>>(ench, encl, ckh, ckl, nullptr, nullptr, kh, kl, D_, D_, 3, 1.0f, 0, 0, 0, nullptr);
    gemm_mma<<<gDD, blk, GMMA_SMEM>>>(ench, encl, cvh, cvl, nullptr, nullptr, vh, vl, D_, D_, 3, 1.0f, 0, 0, 0, nullptr);
    attn_mma<<<gA, blk, AT_SMEM>>>(qh, ql, kh, kl, vh, vl, relpos, aoh, aol, 0, 0);
    gemm_mma<<<gDD, blk, GMMA_SMEM>>>(aoh, aol, coh, col_, y, x1, nullptr, nullptr, D_, D_, 0, 1.0f, 0, 0, 0, nullptr);

    // ---- MLP + adapter ----
    rmsnorm_k<<<B_*L_, blk>>>(y, ln3, xnh, xnl);
    gemm_mma<<<gDF, blk, GMMA_SMEM>>>(xnh, xnl, w0h, w0l, h0, nullptr, nullptr, nullptr, D_, F_, 0, 1.0f, 0, 0, 0, nullptr);
    gemm_mma<<<gDF, blk, GMMA_SMEM>>>(xnh, xnl, w1h, w1l, h1, nullptr, nullptr, nullptr, D_, F_, 0, 1.0f, 0, 0, 0, nullptr);
    gated_k<<<(B_*L_*F_/4)/256, blk>>>(h0, h1, gh, gl);
    gemm_mma<<<gDD, blk, GMMA_SMEM>>>(gh, gl, wmh, wml, out, y, nullptr, nullptr, F_, D_, 0, 1.0f, 0, 0, 0, nullptr);

    gemm_mma<<<dim3(1, 8, 4), blk, GMMA_SMEM>>>(xnh, xnl, adh, adl, nullptr, nullptr, azh, azl,
                                                D_, 128, 4, 1.0f,
                                                (size_t)L_*D_, (size_t)D_*128, (size_t)L_*A_, abd);
    gemm_mma<<<dim3(16, 8, 4), blk, GMMA_SMEM>>>(azh, azl, auh, aul, out, nullptr, nullptr, nullptr,
                                                 A_, D_, 5, 1.0f,
                                                 (size_t)L_*A_, (size_t)A_*D_, (size_t)L_*D_, abu);
}